// round 8
// baseline (speedup 1.0000x reference)
#include <cuda_runtime.h>

// out[b,e] = sparsity[b,e] * sum_h hs[b,h] * ws[e,h]
//   ws[e,h] = sum_n weight[e,h,n]   (32 MB)  -> kernel 1, pure streaming (PROTECTED, ~5.5us)
//   hs + dot                        (4 MB)   -> kernel 2, SINGLE WAVE (128 blocks), MLP=8
// A=1, B=32, M=32, H=1024, E=8, N=1024.

#define Bn 32
#define Mn 32
#define Hn 1024
#define En 8
#define Nn 1024

__device__ float g_wsT[Hn * En];   // wsT[h*8 + e]  (32 KB, L2-resident)

// ---- Kernel 1: pure weight row-sum streaming (R5 verbatim).
__global__ void __launch_bounds__(256) weight_kernel(
    const float* __restrict__ weight,
    float* __restrict__ out)
{
    const int tid  = threadIdx.x;
    const int lane = tid & 31;
    const int wid  = tid >> 5;
    const int r0   = blockIdx.x * 16 + wid * 2;

    const float4* rowA = reinterpret_cast<const float4*>(weight + (size_t)r0 * Nn);
    const float4* rowB = reinterpret_cast<const float4*>(weight + (size_t)(r0 + 1) * Nn);

    float s0 = 0.f, s1 = 0.f;
    #pragma unroll
    for (int k = 0; k < Nn / 4 / 32; k++) {
        float4 a = rowA[lane + k * 32];
        float4 b = rowB[lane + k * 32];
        s0 += (a.x + a.y) + (a.z + a.w);
        s1 += (b.x + b.y) + (b.z + b.w);
    }
    #pragma unroll
    for (int off = 16; off > 0; off >>= 1) {
        s0 += __shfl_xor_sync(0xffffffffu, s0, off);
        s1 += __shfl_xor_sync(0xffffffffu, s1, off);
    }
    if (lane == 0) {
        const int e  = r0 >> 10;
        const int h0 = r0 & (Hn - 1);
        g_wsT[h0 * En + e]       = s0;
        g_wsT[(h0 + 1) * En + e] = s1;
    }
    if (blockIdx.x == 0) out[tid] = 0.f;   // zero all 256 outputs
}

// ---- Kernel 2: hidden reduce + dot, SINGLE WAVE.
// 128 blocks x 256 threads. Block (b, q): b = bid>>2, q = bid&3, h in [q*256, q*256+256).
// Phase 1: thread (g = tid>>6, c = tid&63) sums 8 m-rows at float4 column c
//          -> 8 independent LDG.128 in flight per thread (MLP=8).
// Phase 2: thread tid owns h = q*256+tid; hs from smem, ws via 2 coalesced float4.
// Phase 3: block-reduce p[8], 8 REDs into out.
__global__ void __launch_bounds__(256) hidden_dot_kernel(
    const float* __restrict__ hidden,
    const float* __restrict__ sparsity,
    float* __restrict__ out)
{
    const int bid  = blockIdx.x;
    const int tid  = threadIdx.x;
    const int lane = tid & 31;
    const int wid  = tid >> 5;
    const int b    = bid >> 2;          // [0,32)
    const int q    = bid & 3;           // h-quarter

    // ---- Phase 1: m-reduction, contiguous along h, 8 loads in flight ----
    const int g = tid >> 6;             // m-group: m in [g*8, g*8+8)
    const int c = tid & 63;             // float4 column within the 256-h quarter
    const float4* H4 = reinterpret_cast<const float4*>(hidden);
    const size_t base = (size_t)b * Mn * (Hn / 4) + (size_t)(g * 8) * (Hn / 4)
                      + q * 64 + c;

    float4 acc = make_float4(0.f, 0.f, 0.f, 0.f);
    #pragma unroll
    for (int mm = 0; mm < 8; mm++) {    // 8 independent LDG.128
        float4 v = H4[base + (size_t)mm * (Hn / 4)];
        acc.x += v.x; acc.y += v.y; acc.z += v.z; acc.w += v.w;
    }

    __shared__ float4 sm4[4][64];       // [g][c], 4 KB
    sm4[g][c] = acc;
    __syncthreads();

    // ---- Phase 2: per-h dot against wsT ----
    const float* sm_f = reinterpret_cast<const float*>(sm4);   // [g][256]
    float hs = sm_f[tid] + sm_f[256 + tid] + sm_f[512 + tid] + sm_f[768 + tid];

    const int h = q * 256 + tid;
    const float4* wt = reinterpret_cast<const float4*>(g_wsT + h * En);
    const float4 w0 = wt[0], w1 = wt[1];   // warp reads 1 KB contiguous

    float p[8] = { hs * w0.x, hs * w0.y, hs * w0.z, hs * w0.w,
                   hs * w1.x, hs * w1.y, hs * w1.z, hs * w1.w };

    // ---- Phase 3: reduce across 256 threads ----
    #pragma unroll
    for (int off = 16; off > 0; off >>= 1)
        #pragma unroll
        for (int e = 0; e < 8; e++)
            p[e] += __shfl_xor_sync(0xffffffffu, p[e], off);

    __shared__ float wsum[8][8];        // [warp][e]
    if (lane == 0)
        #pragma unroll
        for (int e = 0; e < 8; e++) wsum[wid][e] = p[e];
    __syncthreads();

    if (tid < En) {
        float v = 0.f;
        #pragma unroll
        for (int w = 0; w < 8; w++) v += wsum[w][tid];
        const int idx = b * En + tid;
        atomicAdd(&out[idx], v * sparsity[idx]);   // 8 REDs/block, 1024 total
    }
}

extern "C" void kernel_launch(void* const* d_in, const int* in_sizes, int n_in,
                              void* d_out, int out_size)
{
    const float* hidden   = (const float*)d_in[0];
    const float* sparsity = (const float*)d_in[1];
    const float* weight   = (const float*)d_in[2];
    float* out = (float*)d_out;

    weight_kernel<<<(En * Hn) / 16, 256>>>(weight, out);           // 512 blocks
    hidden_dot_kernel<<<Bn * 4, 256>>>(hidden, sparsity, out);     // 128 blocks, 1 wave
}